// round 4
// baseline (speedup 1.0000x reference)
#include <cuda_runtime.h>

// DeepAR forward: 2-layer LSTM (H=64), T=383 steps, 16384 independent seqs.
// Persistent: 256 CTAs x 256 threads, 1 CTA/SM (smem-bound by 192KB fp32
// weights), each CTA owns 64 seqs end-to-end.
//
// R3 change: the CTA's four 2-warp seq-groups share NO mutable state
// (h/x/out are partitioned by group; weights read-only), so all per-step
// __syncthreads() are replaced by per-group named barriers (bar.sync id,64).
// Groups drift in phase; each SMSP hosts warps of two different groups, so
// one group's MUFU/activation + barrier + LDG phases overlap another
// group's fma.rn.f32x2 phases -> fma pipe fed near-continuously.

#define TPB 256
#define SEQ 64          // sequences per CTA
#define NCTA 256        // 256 * 64 = 16384 sequences
#define NSTEP 383
#define HP 66           // h-state pitch (2-bank skew for STS, 8B-aligned pairs)

// shared layout (floats)
#define OFF_WT0 0               // [64][256]  W_hh0^T            16384
#define OFF_WT1 16384           // [128][256] [W_ih1;W_hh1]^T    32768
#define OFF_H0  49152           // [64][HP]                       4224
#define OFF_H1  53376           // [64][HP]                       4224
#define OFF_XS  57600           // [64][5]  prev + 4 covariates    320
#define OFF_HW  57920           // head_W (2x64)                   128
#define OFF_HB  58048           // head_b                            2
#define SM_FLOATS 58050
#define SM_BYTES (SM_FLOATS * 4)

typedef unsigned long long ull;

static __device__ __forceinline__ ull pk2(float a, float b) {
    ull r; asm("mov.b64 %0, {%1, %2};" : "=l"(r) : "f"(a), "f"(b)); return r;
}
static __device__ __forceinline__ void upk2(ull v, float& a, float& b) {
    asm("mov.b64 {%0, %1}, %2;" : "=f"(a), "=f"(b) : "l"(v));
}
static __device__ __forceinline__ ull fma2(ull a, ull b, ull c) {
    ull d; asm("fma.rn.f32x2 %0, %1, %2, %3;" : "=l"(d) : "l"(a), "l"(b), "l"(c)); return d;
}

static __device__ __forceinline__ float sigm_(float x) {
    return __fdividef(1.f, 1.f + __expf(-x));
}
static __device__ __forceinline__ float tanh_(float x) {
    float e = __expf(2.f * x);
    return 1.f - __fdividef(2.f, e + 1.f);
}

// 64-thread seq-group barrier (ids 1..4; 0 is reserved for __syncthreads).
#define GBAR() asm volatile("bar.sync %0, 64;" :: "r"(sg + 1) : "memory")

// acc[g][pair] += W^T[j][g*64+u] * h[j][pair] over 64 j-rows.
static __device__ __forceinline__ void mv64(ull (&acc)[4][8],
                                            const float* __restrict__ W,
                                            const float* __restrict__ H,
                                            int u) {
#pragma unroll 8
    for (int j = 0; j < 64; j++) {
        const float* wr = W + j * 256 + u;
        float w0 = wr[0], w1 = wr[64], w2 = wr[128], w3 = wr[192];
        ull W0 = pk2(w0, w0), W1 = pk2(w1, w1), W2 = pk2(w2, w2), W3 = pk2(w3, w3);
        const ull* hr = (const ull*)(H + j * HP);
#pragma unroll
        for (int p = 0; p < 8; p++) {
            ull h = hr[p];
            acc[0][p] = fma2(W0, h, acc[0][p]);
            acc[1][p] = fma2(W1, h, acc[1][p]);
            acc[2][p] = fma2(W2, h, acc[2][p]);
            acc[3][p] = fma2(W3, h, acc[3][p]);
        }
    }
}

extern "C" __global__ void __launch_bounds__(TPB, 1)
deepar_kernel(const float* __restrict__ hist,   // (32,336,512,5)
              const float* __restrict__ fut,    // (32, 48,512,5)
              const float* __restrict__ emb_W,  // (32,1)
              const float* __restrict__ emb_b,  // (32)
              const float* __restrict__ W_ih0,  // (256,36)
              const float* __restrict__ W_hh0,  // (256,64)
              const float* __restrict__ b_ih0,
              const float* __restrict__ b_hh0,
              const float* __restrict__ W_ih1,  // (256,64)
              const float* __restrict__ W_hh1,  // (256,64)
              const float* __restrict__ b_ih1,
              const float* __restrict__ b_hh1,
              const float* __restrict__ head_W, // (2,64)
              const float* __restrict__ head_b, // (2)
              float* __restrict__ out)          // (32,48,512,2)
{
    extern __shared__ float sm[];
    float* Wt0 = sm + OFF_WT0;
    float* Wt1 = sm + OFF_WT1;
    float* h0T = sm + OFF_H0;
    float* h1T = sm + OFF_H1;
    float* xs  = sm + OFF_XS;
    float* hw  = sm + OFF_HW;
    float* hb  = sm + OFF_HB;

    const int tid = threadIdx.x;
    const int u = tid & 63;         // hidden unit this thread owns
    const int sg = tid >> 6;        // sequence group 0..3 (16 seqs, 2 warps)
    const int sbase = sg * 16;      // local seq base of this group
    const int gbase = blockIdx.x * SEQ;

    // ---- load weights into shared (transposed: [j][row]) ----
    for (int e = tid; e < 256 * 64; e += TPB) {
        int row = e >> 6, j = e & 63;
        Wt0[j * 256 + row] = W_hh0[e];
        Wt1[j * 256 + row] = W_ih1[e];
        Wt1[(64 + j) * 256 + row] = W_hh1[e];
    }
    for (int e = tid; e < 64 * HP; e += TPB) { h0T[e] = 0.f; h1T[e] = 0.f; }
    if (tid < 128) hw[tid] = head_W[tid];
    if (tid < 2)   hb[tid] = head_b[tid];

    // ---- fold rank-1 embedding into per-gate scalar coefficients ----
    float v1r[4], v2r[4], wcr[4][4], b1r[4];
#pragma unroll
    for (int g = 0; g < 4; g++) {
        int r = g * 64 + u;
        const float* wr = W_ih0 + r * 36;
        float a = 0.f, bb = 0.f;
#pragma unroll
        for (int e = 0; e < 32; e++) {
            a  = fmaf(wr[e], emb_W[e], a);
            bb = fmaf(wr[e], emb_b[e], bb);
        }
        v1r[g] = a;
        v2r[g] = bb + b_ih0[r] + b_hh0[r];
#pragma unroll
        for (int k = 0; k < 4; k++) wcr[g][k] = wr[32 + k];
        b1r[g] = b_ih1[r] + b_hh1[r];
    }

    float c0v[16], c1v[16];
#pragma unroll
    for (int i = 0; i < 16; i++) { c0v[i] = 0.f; c1v[i] = 0.f; }

    // my sequence for staging/head duty (u < 16 threads of each group)
    const int mys = sbase + (u & 15);
    const int mygs = gbase + mys;
    const int myb = mygs >> 9, myn = mygs & 511;

    __syncthreads();   // weights + h init visible to all groups

    for (int t = 0; t < NSTEP; t++) {
        // ---- stage x_t for this group's 16 seqs (threads u<16) ----
        if (u < 16) {
            const float* s1 = (t < 336)
                ? hist + (((size_t)myb * 336 + t) * 512 + myn) * 5
                : fut  + (((size_t)myb * 48 + (t - 336)) * 512 + myn) * 5;
            int tc = t + 1;
            const float* s2 = (tc < 336)
                ? hist + (((size_t)myb * 336 + tc) * 512 + myn) * 5
                : fut  + (((size_t)myb * 48 + (tc - 336)) * 512 + myn) * 5;
            float* xp = xs + mys * 5;
            xp[0] = s1[0];
            xp[1] = s2[1]; xp[2] = s2[2]; xp[3] = s2[3]; xp[4] = s2[4];
        }
        GBAR();   // x visible within group

        // ---- layer 0 gates: pre0 + W_hh0 @ h0 ----
        ull acc[4][8];
#pragma unroll
        for (int p = 0; p < 8; p++) {
            const float* xa = xs + (sbase + 2 * p) * 5;
            const float* xb = xa + 5;
#pragma unroll
            for (int g = 0; g < 4; g++) {
                float lo = v2r[g], hi = v2r[g];
                lo = fmaf(xa[0], v1r[g], lo);
                hi = fmaf(xb[0], v1r[g], hi);
#pragma unroll
                for (int k = 0; k < 4; k++) {
                    lo = fmaf(xa[1 + k], wcr[g][k], lo);
                    hi = fmaf(xb[1 + k], wcr[g][k], hi);
                }
                acc[g][p] = pk2(lo, hi);
            }
        }
        mv64(acc, Wt0, h0T + sbase, u);
        GBAR();   // group done reading old h0

        // ---- layer 0 cell update (packed 8B h stores) ----
        {
            const int hbase = u * HP + sbase;
#pragma unroll
            for (int p = 0; p < 8; p++) {
                float i0, i1, f0, f1, g0, g1, o0, o1;
                upk2(acc[0][p], i0, i1);
                upk2(acc[1][p], f0, f1);
                upk2(acc[2][p], g0, g1);
                upk2(acc[3][p], o0, o1);
                float ca = sigm_(f0) * c0v[2 * p]     + sigm_(i0) * tanh_(g0);
                float cb = sigm_(f1) * c0v[2 * p + 1] + sigm_(i1) * tanh_(g1);
                c0v[2 * p] = ca; c0v[2 * p + 1] = cb;
                *(ull*)(h0T + hbase + 2 * p) =
                    pk2(sigm_(o0) * tanh_(ca), sigm_(o1) * tanh_(cb));
            }
        }
        GBAR();   // new h0 visible within group

        // ---- layer 1 gates: b1 + W_ih1 @ h0_new + W_hh1 @ h1_old ----
#pragma unroll
        for (int p = 0; p < 8; p++) {
#pragma unroll
            for (int g = 0; g < 4; g++) acc[g][p] = pk2(b1r[g], b1r[g]);
        }
        mv64(acc, Wt1, h0T + sbase, u);
        mv64(acc, Wt1 + 64 * 256, h1T + sbase, u);
        GBAR();   // group done reading old h1

        // ---- layer 1 cell update ----
        {
            const int hbase = u * HP + sbase;
#pragma unroll
            for (int p = 0; p < 8; p++) {
                float i0, i1, f0, f1, g0, g1, o0, o1;
                upk2(acc[0][p], i0, i1);
                upk2(acc[1][p], f0, f1);
                upk2(acc[2][p], g0, g1);
                upk2(acc[3][p], o0, o1);
                float ca = sigm_(f0) * c1v[2 * p]     + sigm_(i0) * tanh_(g0);
                float cb = sigm_(f1) * c1v[2 * p + 1] + sigm_(i1) * tanh_(g1);
                c1v[2 * p] = ca; c1v[2 * p + 1] = cb;
                *(ull*)(h1T + hbase + 2 * p) =
                    pk2(sigm_(o0) * tanh_(ca), sigm_(o1) * tanh_(cb));
            }
        }
        GBAR();   // new h1 visible within group

        // ---- head (last 48 steps; this group's 16 seqs, threads u<16) ----
        if (t >= 335 && u < 16) {
            float p0 = hb[0], p1 = hb[1];
#pragma unroll 8
            for (int j = 0; j < 64; j++) {
                float v = fmaxf(h1T[j * HP + mys], 0.f);
                p0 = fmaf(v, hw[j], p0);
                p1 = fmaf(v, hw[64 + j], p1);
            }
            float sp = (p1 > 15.f) ? p1 : log1pf(__expf(p1));
            ((float2*)out)[((size_t)myb * 48 + (t - 335)) * 512 + myn] =
                make_float2(p0, sp);
        }
        // next h1 overwrite is 4 group-barriers away -> head read is safe
    }
}

extern "C" void kernel_launch(void* const* d_in, const int* in_sizes, int n_in,
                              void* d_out, int out_size) {
    (void)in_sizes; (void)n_in; (void)out_size;
    const float* hist   = (const float*)d_in[0];
    const float* fut    = (const float*)d_in[1];
    const float* emb_W  = (const float*)d_in[2];
    const float* emb_b  = (const float*)d_in[3];
    const float* W_ih0  = (const float*)d_in[4];
    const float* W_hh0  = (const float*)d_in[5];
    const float* b_ih0  = (const float*)d_in[6];
    const float* b_hh0  = (const float*)d_in[7];
    const float* W_ih1  = (const float*)d_in[8];
    const float* W_hh1  = (const float*)d_in[9];
    const float* b_ih1  = (const float*)d_in[10];
    const float* b_hh1  = (const float*)d_in[11];
    const float* head_W = (const float*)d_in[12];
    const float* head_b = (const float*)d_in[13];
    float* out = (float*)d_out;

    cudaFuncSetAttribute(deepar_kernel,
                         cudaFuncAttributeMaxDynamicSharedMemorySize, SM_BYTES);

    deepar_kernel<<<NCTA, TPB, SM_BYTES>>>(
        hist, fut, emb_W, emb_b,
        W_ih0, W_hh0, b_ih0, b_hh0,
        W_ih1, W_hh1, b_ih1, b_hh1,
        head_W, head_b, out);
}

// round 5
// speedup vs baseline: 1.1662x; 1.1662x over previous
#include <cuda_runtime.h>

// DeepAR forward: 2-layer LSTM (H=64), T=383 steps, 16384 independent seqs.
// Persistent: 296 CTAs (2 perfectly balanced waves on 148 SMs) x 256 threads,
// 56 seqs/CTA (tail clamped -> bit-identical duplicate computation).
// Weights in smem as per-unit gate quads (LDS.128); h-state in smem
// (transposed [j][s], pairs 8B-aligned); c-state in registers.
// Inner product: Blackwell packed fma.rn.f32x2, 2 seqs per lane.
// x(t+1) prefetched into registers at step top, written to a double-buffered
// staging area at step bottom -> LDG latency off the critical path, 4 barriers.

#define TPB 256
#define SEQ 56          // sequences per CTA (4 groups x 14)
#define GRP 14          // seqs per group
#define NPAIR 7         // seq pairs per thread
#define NCTA 296        // 2 x 148 -> two full waves
#define NSTEP 383
#define NSEQ_TOT 16384
#define HP 58           // h-state row pitch (even -> 8B-aligned pairs)

// shared layout (floats)
#define OFF_WT0 0               // [64][64] float4 quads   16384
#define OFF_WT1 16384           // [128][64] float4 quads  32768
#define OFF_H0  49152           // [64][HP]                 3712
#define OFF_H1  52864           // [64][HP]                 3712
#define OFF_XS  56576           // 2 x [64][5] double-buf    640
#define OFF_HW  57216           // head_W (2x64)             128
#define OFF_HB  57344           // head_b                      2
#define SM_FLOATS 57346
#define SM_BYTES (SM_FLOATS * 4)

typedef unsigned long long ull;

static __device__ __forceinline__ ull pk2(float a, float b) {
    ull r; asm("mov.b64 %0, {%1, %2};" : "=l"(r) : "f"(a), "f"(b)); return r;
}
static __device__ __forceinline__ void upk2(ull v, float& a, float& b) {
    asm("mov.b64 {%0, %1}, %2;" : "=f"(a), "=f"(b) : "l"(v));
}
static __device__ __forceinline__ ull fma2(ull a, ull b, ull c) {
    ull d; asm("fma.rn.f32x2 %0, %1, %2, %3;" : "=l"(d) : "l"(a), "l"(b), "l"(c)); return d;
}

static __device__ __forceinline__ float sigm_(float x) {
    return __fdividef(1.f, 1.f + __expf(-x));
}
static __device__ __forceinline__ float tanh_(float x) {
    float e = __expf(2.f * x);
    return 1.f - __fdividef(2.f, e + 1.f);
}

// acc[g][p] += W^T[j][g*64+u] * h[j][pair p] over nj rows.
// Wq: per-j quads (4 gate weights of unit u in one float4 -> LDS.128).
static __device__ __forceinline__ void mv64(ull (&acc)[4][NPAIR],
                                            const float4* __restrict__ Wq,
                                            const float* __restrict__ H,
                                            int u) {
#pragma unroll 8
    for (int j = 0; j < 64; j++) {
        float4 w = Wq[j * 64 + u];
        ull W0 = pk2(w.x, w.x), W1 = pk2(w.y, w.y);
        ull W2 = pk2(w.z, w.z), W3 = pk2(w.w, w.w);
        const ull* hr = (const ull*)(H + j * HP);
#pragma unroll
        for (int p = 0; p < NPAIR; p++) {
            ull h = hr[p];
            acc[0][p] = fma2(W0, h, acc[0][p]);
            acc[1][p] = fma2(W1, h, acc[1][p]);
            acc[2][p] = fma2(W2, h, acc[2][p]);
            acc[3][p] = fma2(W3, h, acc[3][p]);
        }
    }
}

extern "C" __global__ void __launch_bounds__(TPB, 1)
deepar_kernel(const float* __restrict__ hist,   // (32,336,512,5)
              const float* __restrict__ fut,    // (32, 48,512,5)
              const float* __restrict__ emb_W,  // (32,1)
              const float* __restrict__ emb_b,  // (32)
              const float* __restrict__ W_ih0,  // (256,36)
              const float* __restrict__ W_hh0,  // (256,64)
              const float* __restrict__ b_ih0,
              const float* __restrict__ b_hh0,
              const float* __restrict__ W_ih1,  // (256,64)
              const float* __restrict__ W_hh1,  // (256,64)
              const float* __restrict__ b_ih1,
              const float* __restrict__ b_hh1,
              const float* __restrict__ head_W, // (2,64)
              const float* __restrict__ head_b, // (2)
              float* __restrict__ out)          // (32,48,512,2)
{
    extern __shared__ float sm[];
    float4* Wt0q = (float4*)(sm + OFF_WT0);
    float4* Wt1q = (float4*)(sm + OFF_WT1);
    float* h0T = sm + OFF_H0;
    float* h1T = sm + OFF_H1;
    float* xs  = sm + OFF_XS;     // two buffers of 320 floats
    float* hw  = sm + OFF_HW;
    float* hb  = sm + OFF_HB;

    const int tid = threadIdx.x;
    const int u = tid & 63;         // hidden unit this thread owns
    const int sg = tid >> 6;        // sequence group 0..3
    const int sbase = sg * GRP;     // local seq base (even -> 8B aligned)
    const int gbase = blockIdx.x * SEQ;

    // ---- weights -> smem as per-unit gate quads: Wq[j][u] = W[{0..3}*64+u][j]
    for (int e = tid; e < 64 * 64; e += TPB) {
        int j = e >> 6, uu = e & 63;
        Wt0q[j * 64 + uu] = make_float4(W_hh0[uu * 64 + j],
                                        W_hh0[(64 + uu) * 64 + j],
                                        W_hh0[(128 + uu) * 64 + j],
                                        W_hh0[(192 + uu) * 64 + j]);
    }
    for (int e = tid; e < 128 * 64; e += TPB) {
        int j = e >> 6, uu = e & 63;
        const float* src = (j < 64) ? (W_ih1 + j) : (W_hh1 + (j - 64));
        Wt1q[j * 64 + uu] = make_float4(src[uu * 64],
                                        src[(64 + uu) * 64],
                                        src[(128 + uu) * 64],
                                        src[(192 + uu) * 64]);
    }
    for (int e = tid; e < 64 * HP; e += TPB) { h0T[e] = 0.f; h1T[e] = 0.f; }
    if (tid < 128) hw[tid] = head_W[tid];
    if (tid < 2)   hb[tid] = head_b[tid];

    // ---- fold rank-1 embedding into per-gate scalar coefficients ----
    float v1r[4], v2r[4], wcr[4][4], b1r[4];
#pragma unroll
    for (int g = 0; g < 4; g++) {
        int r = g * 64 + u;
        const float* wr = W_ih0 + r * 36;
        float a = 0.f, bb = 0.f;
#pragma unroll
        for (int e = 0; e < 32; e++) {
            a  = fmaf(wr[e], emb_W[e], a);
            bb = fmaf(wr[e], emb_b[e], bb);
        }
        v1r[g] = a;
        v2r[g] = bb + b_ih0[r] + b_hh0[r];
#pragma unroll
        for (int k = 0; k < 4; k++) wcr[g][k] = wr[32 + k];
        b1r[g] = b_ih1[r] + b_hh1[r];
    }

    float c0v[2 * NPAIR], c1v[2 * NPAIR];
#pragma unroll
    for (int i = 0; i < 2 * NPAIR; i++) { c0v[i] = 0.f; c1v[i] = 0.f; }

    // staging/head duty: first GRP threads of each group, clamped tail seq
    const bool duty = (u < GRP);
    const int mys = sbase + (u < GRP ? u : 0);
    int mygs = gbase + mys; if (mygs > NSEQ_TOT - 1) mygs = NSEQ_TOT - 1;
    const int myb = mygs >> 9, myn = mygs & 511;

    // stage x for t=0 into buffer 0
    if (duty) {
        const float* s1 = hist + (((size_t)myb * 336) * 512 + myn) * 5;
        const float* s2 = hist + (((size_t)myb * 336 + 1) * 512 + myn) * 5;
        float* xp = xs + mys * 5;
        xp[0] = s1[0];
        xp[1] = s2[1]; xp[2] = s2[2]; xp[3] = s2[3]; xp[4] = s2[4];
    }
    __syncthreads();

    for (int t = 0; t < NSTEP; t++) {
        const float* cur = xs + (t & 1) * 320;
        float* nxt = xs + ((t + 1) & 1) * 320;

        // ---- prefetch x(t+1) into registers (latency hidden by FMA phase)
        float xr0, xr1, xr2, xr3, xr4;
        const bool pf = duty && (t + 1 < NSTEP);
        if (pf) {
            int tn = t + 1;
            const float* s1 = (tn < 336)
                ? hist + (((size_t)myb * 336 + tn) * 512 + myn) * 5
                : fut  + (((size_t)myb * 48 + (tn - 336)) * 512 + myn) * 5;
            int tc = tn + 1;
            const float* s2 = (tc < 336)
                ? hist + (((size_t)myb * 336 + tc) * 512 + myn) * 5
                : fut  + (((size_t)myb * 48 + (tc - 336)) * 512 + myn) * 5;
            xr0 = s1[0];
            xr1 = s2[1]; xr2 = s2[2]; xr3 = s2[3]; xr4 = s2[4];
        }

        // ---- layer 0 gates: pre0(x) + W_hh0 @ h0 ----
        ull acc[4][NPAIR];
#pragma unroll
        for (int p = 0; p < NPAIR; p++) {
            const float* xa = cur + (sbase + 2 * p) * 5;
            const float* xb = xa + 5;
#pragma unroll
            for (int g = 0; g < 4; g++) {
                float lo = v2r[g], hi = v2r[g];
                lo = fmaf(xa[0], v1r[g], lo);
                hi = fmaf(xb[0], v1r[g], hi);
#pragma unroll
                for (int k = 0; k < 4; k++) {
                    lo = fmaf(xa[1 + k], wcr[g][k], lo);
                    hi = fmaf(xb[1 + k], wcr[g][k], hi);
                }
                acc[g][p] = pk2(lo, hi);
            }
        }
        mv64(acc, Wt0q, h0T + sbase, u);
        __syncthreads();   // A: old h0 fully read

        // ---- layer 0 cell update (packed 8B h stores) ----
        {
            const int hbase = u * HP + sbase;
#pragma unroll
            for (int p = 0; p < NPAIR; p++) {
                float i0, i1, f0, f1, g0, g1, o0, o1;
                upk2(acc[0][p], i0, i1);
                upk2(acc[1][p], f0, f1);
                upk2(acc[2][p], g0, g1);
                upk2(acc[3][p], o0, o1);
                float ca = sigm_(f0) * c0v[2 * p]     + sigm_(i0) * tanh_(g0);
                float cb = sigm_(f1) * c0v[2 * p + 1] + sigm_(i1) * tanh_(g1);
                c0v[2 * p] = ca; c0v[2 * p + 1] = cb;
                *(ull*)(h0T + hbase + 2 * p) =
                    pk2(sigm_(o0) * tanh_(ca), sigm_(o1) * tanh_(cb));
            }
        }
        __syncthreads();   // B: new h0 visible

        // ---- layer 1 gates: b1 + W_ih1 @ h0_new + W_hh1 @ h1_old ----
#pragma unroll
        for (int p = 0; p < NPAIR; p++) {
#pragma unroll
            for (int g = 0; g < 4; g++) acc[g][p] = pk2(b1r[g], b1r[g]);
        }
        mv64(acc, Wt1q, h0T + sbase, u);
        mv64(acc, Wt1q + 64 * 64, h1T + sbase, u);
        __syncthreads();   // C: old h1 fully read

        // ---- layer 1 cell update + stage x(t+1) ----
        {
            const int hbase = u * HP + sbase;
#pragma unroll
            for (int p = 0; p < NPAIR; p++) {
                float i0, i1, f0, f1, g0, g1, o0, o1;
                upk2(acc[0][p], i0, i1);
                upk2(acc[1][p], f0, f1);
                upk2(acc[2][p], g0, g1);
                upk2(acc[3][p], o0, o1);
                float ca = sigm_(f0) * c1v[2 * p]     + sigm_(i0) * tanh_(g0);
                float cb = sigm_(f1) * c1v[2 * p + 1] + sigm_(i1) * tanh_(g1);
                c1v[2 * p] = ca; c1v[2 * p + 1] = cb;
                *(ull*)(h1T + hbase + 2 * p) =
                    pk2(sigm_(o0) * tanh_(ca), sigm_(o1) * tanh_(cb));
            }
        }
        if (pf) {
            float* xp = nxt + mys * 5;
            xp[0] = xr0; xp[1] = xr1; xp[2] = xr2; xp[3] = xr3; xp[4] = xr4;
        }
        __syncthreads();   // D: new h1 + x(t+1) visible

        // ---- head (last 48 steps; duty threads, 1 seq each) ----
        if (t >= 335 && duty) {
            float p0 = hb[0], p1 = hb[1];
#pragma unroll 8
            for (int j = 0; j < 64; j++) {
                float v = fmaxf(h1T[j * HP + mys], 0.f);
                p0 = fmaf(v, hw[j], p0);
                p1 = fmaf(v, hw[64 + j], p1);
            }
            float sp = (p1 > 15.f) ? p1 : log1pf(__expf(p1));
            // clamped duplicates write bit-identical values -> deterministic
            ((float2*)out)[((size_t)myb * 48 + (t - 335)) * 512 + myn] =
                make_float2(p0, sp);
        }
        // h1T next overwritten after bar C of step t+1 -> head read is safe
    }
}

extern "C" void kernel_launch(void* const* d_in, const int* in_sizes, int n_in,
                              void* d_out, int out_size) {
    (void)in_sizes; (void)n_in; (void)out_size;
    const float* hist   = (const float*)d_in[0];
    const float* fut    = (const float*)d_in[1];
    const float* emb_W  = (const float*)d_in[2];
    const float* emb_b  = (const float*)d_in[3];
    const float* W_ih0  = (const float*)d_in[4];
    const float* W_hh0  = (const float*)d_in[5];
    const float* b_ih0  = (const float*)d_in[6];
    const float* b_hh0  = (const float*)d_in[7];
    const float* W_ih1  = (const float*)d_in[8];
    const float* W_hh1  = (const float*)d_in[9];
    const float* b_ih1  = (const float*)d_in[10];
    const float* b_hh1  = (const float*)d_in[11];
    const float* head_W = (const float*)d_in[12];
    const float* head_b = (const float*)d_in[13];
    float* out = (float*)d_out;

    cudaFuncSetAttribute(deepar_kernel,
                         cudaFuncAttributeMaxDynamicSharedMemorySize, SM_BYTES);

    deepar_kernel<<<NCTA, TPB, SM_BYTES>>>(
        hist, fut, emb_W, emb_b,
        W_ih0, W_hh0, b_ih0, b_hh0,
        W_ih1, W_hh1, b_ih1, b_hh1,
        head_W, head_b, out);
}

// round 7
// speedup vs baseline: 1.2480x; 1.0701x over previous
#include <cuda_runtime.h>

// DeepAR forward: 2-layer LSTM (H=64), T=383 steps, 16384 independent seqs.
// Persistent: 296 CTAs (2 full waves on 148 SMs) x 256 threads, 56 seqs/CTA.
// R5/R6: software-pipelined step. Each iteration enters holding acc0(t)
// (layer-0 gate pre-activations). MUFU cell-updates are interleaved, in the
// SAME in-order instruction stream, with independent fma.rn.f32x2 matvec work:
//   U0(t) x (W_hh1 @ h1_old)   and   U1(t) x (next step's layer-0 matvec).
// MUFU-pipe time (~4.5K cyc/SMSP/step) hides under the FMA phases; barriers
// drop from 4 to 2 per step. Per-value arithmetic identical to R4.
// (R6 resubmission: R5 bench was lost to a container infra failure.)

#define TPB 256
#define SEQ 56          // sequences per CTA (4 groups x 14)
#define GRP 14
#define NPAIR 7         // seq pairs per thread
#define NCTA 296        // 2 x 148 -> two full waves
#define NSTEP 383
#define NSEQ_TOT 16384
#define HP 58           // h-state row pitch (even -> 8B-aligned pairs)

// shared layout (floats)
#define OFF_WT0 0               // [64][64] float4 quads   16384
#define OFF_WT1 16384           // [128][64] float4 quads  32768
#define OFF_H0  49152           // [64][HP]                 3712
#define OFF_H1  52864           // [64][HP]                 3712
#define OFF_XS  56576           // 2 x [64][5] double-buf    640
#define OFF_HW  57216           // head_W (2x64)             128
#define OFF_HB  57344           // head_b                      2
#define SM_FLOATS 57346
#define SM_BYTES (SM_FLOATS * 4)

typedef unsigned long long ull;

static __device__ __forceinline__ ull pk2(float a, float b) {
    ull r; asm("mov.b64 %0, {%1, %2};" : "=l"(r) : "f"(a), "f"(b)); return r;
}
static __device__ __forceinline__ void upk2(ull v, float& a, float& b) {
    asm("mov.b64 {%0, %1}, %2;" : "=f"(a), "=f"(b) : "l"(v));
}
static __device__ __forceinline__ ull fma2(ull a, ull b, ull c) {
    ull d; asm("fma.rn.f32x2 %0, %1, %2, %3;" : "=l"(d) : "l"(a), "l"(b), "l"(c)); return d;
}

static __device__ __forceinline__ float sigm_(float x) {
    return __fdividef(1.f, 1.f + __expf(-x));
}
static __device__ __forceinline__ float tanh_(float x) {
    float e = __expf(2.f * x);
    return 1.f - __fdividef(2.f, e + 1.f);
}

// LSTM cell update for one sequence pair (same math/order as R4).
#define CELL_UPDATE(accA, cv, hnew, p) do {                                   \
    float i0_, i1_, f0_, f1_, g0_, g1_, o0_, o1_;                             \
    upk2(accA[0][p], i0_, i1_);                                               \
    upk2(accA[1][p], f0_, f1_);                                               \
    upk2(accA[2][p], g0_, g1_);                                               \
    upk2(accA[3][p], o0_, o1_);                                               \
    float ca_ = sigm_(f0_) * cv[2*(p)]     + sigm_(i0_) * tanh_(g0_);         \
    float cb_ = sigm_(f1_) * cv[2*(p)+1]   + sigm_(i1_) * tanh_(g1_);         \
    cv[2*(p)] = ca_; cv[2*(p)+1] = cb_;                                       \
    hnew[p] = pk2(sigm_(o0_) * tanh_(ca_), sigm_(o1_) * tanh_(cb_));          \
} while (0)

// plain matvec: acc[g][p] += Wq[j][u].{xyzw} * h[j][pair p]
static __device__ __forceinline__ void mv64(ull (&acc)[4][NPAIR],
                                            const float4* __restrict__ Wq,
                                            const float* __restrict__ H,
                                            int u) {
#pragma unroll 8
    for (int j = 0; j < 64; j++) {
        float4 w = Wq[j * 64 + u];
        ull W0 = pk2(w.x, w.x), W1 = pk2(w.y, w.y);
        ull W2 = pk2(w.z, w.z), W3 = pk2(w.w, w.w);
        const ull* hr = (const ull*)(H + j * HP);
#pragma unroll
        for (int p = 0; p < NPAIR; p++) {
            ull h = hr[p];
            acc[0][p] = fma2(W0, h, acc[0][p]);
            acc[1][p] = fma2(W1, h, acc[1][p]);
            acc[2][p] = fma2(W2, h, acc[2][p]);
            acc[3][p] = fma2(W3, h, acc[3][p]);
        }
    }
}

// x-fetch: prev target at time t, covariates at time t+1 (t in [0,382])
static __device__ __forceinline__ void ldx(const float* __restrict__ hist,
                                           const float* __restrict__ fut,
                                           int myb, int myn, int t,
                                           float& x0, float& x1, float& x2,
                                           float& x3, float& x4) {
    const float* s1 = (t < 336)
        ? hist + (((size_t)myb * 336 + t) * 512 + myn) * 5
        : fut  + (((size_t)myb * 48 + (t - 336)) * 512 + myn) * 5;
    int tc = t + 1;
    const float* s2 = (tc < 336)
        ? hist + (((size_t)myb * 336 + tc) * 512 + myn) * 5
        : fut  + (((size_t)myb * 48 + (tc - 336)) * 512 + myn) * 5;
    x0 = s1[0];
    x1 = s2[1]; x2 = s2[2]; x3 = s2[3]; x4 = s2[4];
}

extern "C" __global__ void __launch_bounds__(TPB, 1)
deepar_kernel(const float* __restrict__ hist,   // (32,336,512,5)
              const float* __restrict__ fut,    // (32, 48,512,5)
              const float* __restrict__ emb_W,  // (32,1)
              const float* __restrict__ emb_b,  // (32)
              const float* __restrict__ W_ih0,  // (256,36)
              const float* __restrict__ W_hh0,  // (256,64)
              const float* __restrict__ b_ih0,
              const float* __restrict__ b_hh0,
              const float* __restrict__ W_ih1,  // (256,64)
              const float* __restrict__ W_hh1,  // (256,64)
              const float* __restrict__ b_ih1,
              const float* __restrict__ b_hh1,
              const float* __restrict__ head_W, // (2,64)
              const float* __restrict__ head_b, // (2)
              float* __restrict__ out)          // (32,48,512,2)
{
    extern __shared__ float sm[];
    float4* Wt0q = (float4*)(sm + OFF_WT0);
    float4* Wt1q = (float4*)(sm + OFF_WT1);   // [0..63]=W_ih1, [64..127]=W_hh1
    float* h0T = sm + OFF_H0;
    float* h1T = sm + OFF_H1;
    float* xs  = sm + OFF_XS;                 // two buffers of 320 floats
    float* hw  = sm + OFF_HW;
    float* hb  = sm + OFF_HB;

    const int tid = threadIdx.x;
    const int u = tid & 63;
    const int sg = tid >> 6;
    const int sbase = sg * GRP;               // even -> 8B-aligned pairs
    const int gbase = blockIdx.x * SEQ;

    // ---- weights -> smem as per-unit gate quads ----
    for (int e = tid; e < 64 * 64; e += TPB) {
        int j = e >> 6, uu = e & 63;
        Wt0q[j * 64 + uu] = make_float4(W_hh0[uu * 64 + j],
                                        W_hh0[(64 + uu) * 64 + j],
                                        W_hh0[(128 + uu) * 64 + j],
                                        W_hh0[(192 + uu) * 64 + j]);
    }
    for (int e = tid; e < 128 * 64; e += TPB) {
        int j = e >> 6, uu = e & 63;
        const float* src = (j < 64) ? (W_ih1 + j) : (W_hh1 + (j - 64));
        Wt1q[j * 64 + uu] = make_float4(src[uu * 64],
                                        src[(64 + uu) * 64],
                                        src[(128 + uu) * 64],
                                        src[(192 + uu) * 64]);
    }
    for (int e = tid; e < 64 * HP; e += TPB) { h0T[e] = 0.f; h1T[e] = 0.f; }
    if (tid < 128) hw[tid] = head_W[tid];
    if (tid < 2)   hb[tid] = head_b[tid];

    // ---- fold rank-1 embedding into per-gate scalar coefficients ----
    float v1r[4], v2r[4], wcr[4][4], b1r[4];
#pragma unroll
    for (int g = 0; g < 4; g++) {
        int r = g * 64 + u;
        const float* wr = W_ih0 + r * 36;
        float a = 0.f, bb = 0.f;
#pragma unroll
        for (int e = 0; e < 32; e++) {
            a  = fmaf(wr[e], emb_W[e], a);
            bb = fmaf(wr[e], emb_b[e], bb);
        }
        v1r[g] = a;
        v2r[g] = bb + b_ih0[r] + b_hh0[r];
#pragma unroll
        for (int k = 0; k < 4; k++) wcr[g][k] = wr[32 + k];
        b1r[g] = b_ih1[r] + b_hh1[r];
    }

    float c0v[2 * NPAIR], c1v[2 * NPAIR];
#pragma unroll
    for (int i = 0; i < 2 * NPAIR; i++) { c0v[i] = 0.f; c1v[i] = 0.f; }

    const bool duty = (u < GRP);
    const int mys = sbase + (u < GRP ? u : 0);
    int mygs = gbase + mys; if (mygs > NSEQ_TOT - 1) mygs = NSEQ_TOT - 1;
    const int myb = mygs >> 9, myn = mygs & 511;

    // ---- prologue: stage x(0), prefetch x(1) ----
    float xr0, xr1, xr2, xr3, xr4;
    if (duty) {
        float a0, a1, a2, a3, a4;
        ldx(hist, fut, myb, myn, 0, a0, a1, a2, a3, a4);
        float* xp = xs + mys * 5;
        xp[0] = a0; xp[1] = a1; xp[2] = a2; xp[3] = a3; xp[4] = a4;
        ldx(hist, fut, myb, myn, 1, xr0, xr1, xr2, xr3, xr4);
    }
    __syncthreads();   // weights, zero h, x(0) visible

    // acc0(0) = pre0(x(0)) + W_hh0 @ h0(=0)
    ull acc0[4][NPAIR];
#pragma unroll
    for (int p = 0; p < NPAIR; p++) {
        const float* xa = xs + (sbase + 2 * p) * 5;
        const float* xb = xa + 5;
#pragma unroll
        for (int g = 0; g < 4; g++) {
            float lo = v2r[g], hi = v2r[g];
            lo = fmaf(xa[0], v1r[g], lo);
            hi = fmaf(xb[0], v1r[g], hi);
#pragma unroll
            for (int k = 0; k < 4; k++) {
                lo = fmaf(xa[1 + k], wcr[g][k], lo);
                hi = fmaf(xb[1 + k], wcr[g][k], hi);
            }
            acc0[g][p] = pk2(lo, hi);
        }
    }
    mv64(acc0, Wt0q, h0T + sbase, u);
    __syncthreads();   // all pre-loop h0 reads done (S0(0) WAR guard)

    for (int t = 0; t < NSTEP; t++) {
        const bool notlast = (t + 1 < NSTEP);

        // ---- phase 1: U0(t) [MUFU] interleaved with accB = W_hh1 @ h1_old
        ull accB[4][NPAIR];
#pragma unroll
        for (int p = 0; p < NPAIR; p++) {
#pragma unroll
            for (int g = 0; g < 4; g++) accB[g][p] = pk2(b1r[g], b1r[g]);
        }
        ull h0new[NPAIR];
        {
            const float4* Wq = Wt1q + 64 * 64;   // W_hh1 quads
            const float* H = h1T + sbase;
#pragma unroll
            for (int j = 0; j < 64; j++) {
                float4 w = Wq[j * 64 + u];
                ull W0 = pk2(w.x, w.x), W1 = pk2(w.y, w.y);
                ull W2 = pk2(w.z, w.z), W3 = pk2(w.w, w.w);
                const ull* hr = (const ull*)(H + j * HP);
#pragma unroll
                for (int p = 0; p < NPAIR; p++) {
                    ull h = hr[p];
                    accB[0][p] = fma2(W0, h, accB[0][p]);
                    accB[1][p] = fma2(W1, h, accB[1][p]);
                    accB[2][p] = fma2(W2, h, accB[2][p]);
                    accB[3][p] = fma2(W3, h, accB[3][p]);
                }
                if ((j & 7) == 1) {               // 8 slots, 7 pairs
                    const int p = j >> 3;
                    if (p < NPAIR) CELL_UPDATE(acc0, c0v, h0new, p);
                }
            }
        }

        // ---- phase 2: store h0(t); stage x(t+1) ----
        {
            const int hbase = u * HP + sbase;
#pragma unroll
            for (int p = 0; p < NPAIR; p++)
                *(ull*)(h0T + hbase + 2 * p) = h0new[p];
        }
        if (duty && notlast) {
            float* xp = xs + ((t + 1) & 1) * 320 + mys * 5;
            xp[0] = xr0; xp[1] = xr1; xp[2] = xr2; xp[3] = xr3; xp[4] = xr4;
        }
        __syncthreads();   // bar1: h0(t), x(t+1) visible; h1_old reads done

        // prefetch x(t+2) (latency hidden under phases 3-4)
        if (duty && t + 2 < NSTEP)
            ldx(hist, fut, myb, myn, t + 2, xr0, xr1, xr2, xr3, xr4);

        // ---- phase 3: acc1 = accB + W_ih1 @ h0(t) ----
        mv64(accB, Wt1q, h0T + sbase, u);

        // ---- phase 4: U1(t) [MUFU] interleaved with acc0(t+1) matvec ----
        ull h1new[NPAIR];
        if (notlast) {
            const float* cur = xs + ((t + 1) & 1) * 320;
#pragma unroll
            for (int p = 0; p < NPAIR; p++) {
                const float* xa = cur + (sbase + 2 * p) * 5;
                const float* xb = xa + 5;
#pragma unroll
                for (int g = 0; g < 4; g++) {
                    float lo = v2r[g], hi = v2r[g];
                    lo = fmaf(xa[0], v1r[g], lo);
                    hi = fmaf(xb[0], v1r[g], hi);
#pragma unroll
                    for (int k = 0; k < 4; k++) {
                        lo = fmaf(xa[1 + k], wcr[g][k], lo);
                        hi = fmaf(xb[1 + k], wcr[g][k], hi);
                    }
                    acc0[g][p] = pk2(lo, hi);
                }
            }
            const float* H0 = h0T + sbase;
#pragma unroll
            for (int j = 0; j < 64; j++) {
                float4 w = Wt0q[j * 64 + u];
                ull W0 = pk2(w.x, w.x), W1 = pk2(w.y, w.y);
                ull W2 = pk2(w.z, w.z), W3 = pk2(w.w, w.w);
                const ull* hr = (const ull*)(H0 + j * HP);
#pragma unroll
                for (int p = 0; p < NPAIR; p++) {
                    ull h = hr[p];
                    acc0[0][p] = fma2(W0, h, acc0[0][p]);
                    acc0[1][p] = fma2(W1, h, acc0[1][p]);
                    acc0[2][p] = fma2(W2, h, acc0[2][p]);
                    acc0[3][p] = fma2(W3, h, acc0[3][p]);
                }
                if ((j & 7) == 1) {
                    const int p = j >> 3;
                    if (p < NPAIR) CELL_UPDATE(accB, c1v, h1new, p);
                }
            }
        } else {
#pragma unroll
            for (int p = 0; p < NPAIR; p++) CELL_UPDATE(accB, c1v, h1new, p);
        }

        // ---- phase 5: store h1(t) ----
        {
            const int hbase = u * HP + sbase;
#pragma unroll
            for (int p = 0; p < NPAIR; p++)
                *(ull*)(h1T + hbase + 2 * p) = h1new[p];
        }
        __syncthreads();   // bar2: h1(t) visible

        // ---- head (last 48 steps) ----
        if (t >= 335 && duty) {
            float p0 = hb[0], p1 = hb[1];
#pragma unroll 8
            for (int j = 0; j < 64; j++) {
                float v = fmaxf(h1T[j * HP + mys], 0.f);
                p0 = fmaf(v, hw[j], p0);
                p1 = fmaf(v, hw[64 + j], p1);
            }
            float sp = (p1 > 15.f) ? p1 : log1pf(__expf(p1));
            ((float2*)out)[((size_t)myb * 48 + (t - 335)) * 512 + myn] =
                make_float2(p0, sp);
        }
        // h1T next overwritten after bar1 of step t+1 -> head read safe
    }
}

extern "C" void kernel_launch(void* const* d_in, const int* in_sizes, int n_in,
                              void* d_out, int out_size) {
    (void)in_sizes; (void)n_in; (void)out_size;
    const float* hist   = (const float*)d_in[0];
    const float* fut    = (const float*)d_in[1];
    const float* emb_W  = (const float*)d_in[2];
    const float* emb_b  = (const float*)d_in[3];
    const float* W_ih0  = (const float*)d_in[4];
    const float* W_hh0  = (const float*)d_in[5];
    const float* b_ih0  = (const float*)d_in[6];
    const float* b_hh0  = (const float*)d_in[7];
    const float* W_ih1  = (const float*)d_in[8];
    const float* W_hh1  = (const float*)d_in[9];
    const float* b_ih1  = (const float*)d_in[10];
    const float* b_hh1  = (const float*)d_in[11];
    const float* head_W = (const float*)d_in[12];
    const float* head_b = (const float*)d_in[13];
    float* out = (float*)d_out;

    cudaFuncSetAttribute(deepar_kernel,
                         cudaFuncAttributeMaxDynamicSharedMemorySize, SM_BYTES);

    deepar_kernel<<<NCTA, TPB, SM_BYTES>>>(
        hist, fut, emb_W, emb_b,
        W_ih0, W_hh0, b_ih0, b_hh0,
        W_ih1, W_hh1, b_ih1, b_hh1,
        head_W, head_b, out);
}